// round 1
// baseline (speedup 1.0000x reference)
#include <cuda_runtime.h>
#include <math.h>

#define NPART 4096
#define MAXNB 48

// ---------------- device scratch (no allocations allowed) ----------------
__device__ float2 g_pos[NPART];          // packed original positions
__device__ float  g_ang[NPART];          // atan2(ori_im, ori_re)
__device__ float2 g_p0[NPART];           // pos + trans (collision input)
__device__ float2 g_mean;                // global position mean (cms)
__device__ int    g_nb[NPART * MAXNB];   // collision candidate lists
__device__ int    g_ncnt[NPART];

// ---------------- constants (match reference float32 semantics) ----------
#define PI_F      3.1415927410125732f
#define TWO_PI_F  6.2831854820251465f
#define HALF_PI_F 1.5707963705062866f

__device__ __forceinline__ float wrapf(float diff) {
    // matches: where(diff <= -pi, mod(diff, pi), diff); then -2pi if >= pi
    if (diff <= -PI_F) {
        float m = fmodf(diff, PI_F);       // C fmod: sign of dividend
        if (m < 0.0f) m += PI_F;           // -> pythonic mod in [0, pi)
        diff = m;
    }
    if (diff >= PI_F) diff -= TWO_PI_F;
    return diff;
}

// ---------------- K0: pack positions, compute angles ----------------------
__global__ void k_prep(const float* __restrict__ pre, const float* __restrict__ pim,
                       const float* __restrict__ ore, const float* __restrict__ oim) {
    int i = blockIdx.x * blockDim.x + threadIdx.x;
    if (i < NPART) {
        g_pos[i] = make_float2(pre[i], pim[i]);
        g_ang[i] = atan2f(oim[i], ore[i]);
    }
}

// ---------------- K0b: deterministic global mean (cms) --------------------
__global__ void k_mean(const float* __restrict__ pre, const float* __restrict__ pim) {
    __shared__ float sx[1024], sy[1024];
    int t = threadIdx.x;
    float ax = 0.f, ay = 0.f;
#pragma unroll
    for (int k = 0; k < 4; k++) { ax += pre[t + 1024 * k]; ay += pim[t + 1024 * k]; }
    sx[t] = ax; sy[t] = ay;
    __syncthreads();
    for (int s = 512; s > 0; s >>= 1) {
        if (t < s) { sx[t] += sx[t + s]; sy[t] += sy[t + s]; }
        __syncthreads();
    }
    if (t == 0) g_mean = make_float2(sx[0] * (1.0f / 4096.0f), sy[0] * (1.0f / 4096.0f));
}

// ---------------- K1: N^2 pair pass + per-particle epilogue ----------------
__global__ void __launch_bounds__(256) k_main(
    const float* __restrict__ ore, const float* __restrict__ oim,
    const float* __restrict__ deltas, const float* __restrict__ rotn,
    const float* __restrict__ tnr, const float* __restrict__ tni,
    float* __restrict__ out)
{
    const float RO_RC2 = (float)(2.815e-5 * 2.815e-5);   // (RO+RC)^2
    const float RR2    = (float)(8.0e-6 * 8.0e-6);       // RR^2
    const float NB2    = (float)(2.52e-5 * 2.52e-5);     // (8*RC)^2 candidate radius

    int warp = threadIdx.x >> 5;
    int lane = threadIdx.x & 31;
    int i = blockIdx.x * 8 + warp;

    float2 pi_ = g_pos[i];
    float  angi = g_ang[i];

    float osr = 0.f, osi = 0.f, sx = 0.f, sy = 0.f;
    int nr = 0, cnt = 0;
    unsigned lmask = (1u << lane) - 1u;

#pragma unroll 4
    for (int j = lane; j < NPART; j += 32) {
        float2 pj = g_pos[j];
        float dx = pj.x - pi_.x;
        float dy = pj.y - pi_.y;
        float d2 = fmaf(dx, dx, dy * dy);
        bool ro = (d2 <= RO_RC2);
        unsigned mro = __ballot_sync(0xffffffffu, ro);
        if (mro) {   // warp-uniform rare branch (~5% of iterations)
            bool nb = ro && (d2 <= NB2) && (j != i);
            unsigned m = __ballot_sync(0xffffffffu, nb);
            if (nb) {
                int idx = cnt + __popc(m & lmask);
                if (idx < MAXNB) g_nb[i * MAXNB + idx] = j;
            }
            cnt += __popc(m);
            if (ro) {
                osr += __ldg(&ore[j]);
                osi += __ldg(&oim[j]);
                if (d2 <= RR2 && j != i) {
                    float ad = wrapf(angi - __ldg(&g_ang[j]));
                    if (fabsf(ad) < HALF_PI_F) { nr += 1; sx += pj.x; sy += pj.y; }
                }
            }
        }
    }

    // warp reduction
#pragma unroll
    for (int o = 16; o > 0; o >>= 1) {
        osr += __shfl_down_sync(0xffffffffu, osr, o);
        osi += __shfl_down_sync(0xffffffffu, osi, o);
        sx  += __shfl_down_sync(0xffffffffu, sx,  o);
        sy  += __shfl_down_sync(0xffffffffu, sy,  o);
        nr  += __shfl_down_sync(0xffffffffu, nr,  o);
    }

    if (lane == 0) {
        g_ncnt[i] = (cnt < MAXNB) ? cnt : MAXNB;

        float2 mean = g_mean;
        float invn = 1.0f / fmaxf((float)nr, 1.0f);
        float sgn  = (nr > 0) ? 1.0f : 0.0f;
        float Sx = sx * invn - pi_.x * sgn;
        float Sy = sy * invn - pi_.y * sgn;
        float dxr = -Sx, dyr = -Sy;

        float Psx = mean.x - pi_.x;
        float Psy = mean.y - pi_.y;

        float del = deltas[i];
        float cd, sd; sincosf(del, &sd, &cd);
        float lx = Psx * cd - Psy * sd;            // Ps * exp(+i delta)
        float ly = Psx * sd + Psy * cd;
        float rx = Psx * cd + Psy * sd;            // Ps * exp(-i delta)
        float ry = Psy * cd - Psx * sd;

        float no  = fmaxf(sqrtf(osr * osr + osi * osi), 1e-14f);
        float nl  = fmaxf(sqrtf(lx * lx + ly * ly), 1e-14f);
        float nrt = fmaxf(sqrtf(rx * rx + ry * ry), 1e-14f);
        float csl = (lx * osr + ly * osi) / (nl * no);
        float csr = (rx * osr + ry * osi) / (nrt * no);
        float bx = (csl >= csr) ? lx : rx;
        float by = (csl >= csr) ? ly : ry;

        bool hasrep = (dxr * dxr + dyr * dyr) > 0.0f;
        float aa  = hasrep ? atan2f(dyr, dxr) : atan2f(by, bx);
        float att = wrapf(aa - angi);

        float theta = 0.014f * sinf(att)
                    + (rotn[i] * 0.074833147735478508f) * 0.44721359549995793f;
        float cr, sr; sincosf(theta, &sr, &cr);
        float oxi = ore[i], oyi = oim[i];
        float nor = oxi * cr - oyi * sr;           // new_ori = ori * rot
        float noi = oxi * sr + oyi * cr;

        float tnx = ((tnr[i] * 0.70710678118654752f) * 1.6733200530681511e-7f)
                    * 0.44721359549995793f;
        float tny = ((tni[i] * 0.70710678118654752f) * 1.6733200530681511e-7f)
                    * 0.44721359549995793f;
        float trx = 1e-7f * oxi + tnx;             // DT*VEL*ori + tnoise*sqrt(DT)
        float try_ = 1e-7f * oyi + tny;

        g_p0[i] = make_float2(pi_.x + trx, pi_.y + try_);

        out[ 8192 + 2 * i]     = nor;  out[ 8192 + 2 * i + 1] = noi;  // new_ori
        out[16384 + 2 * i]     = osr;  out[16384 + 2 * i + 1] = osi;  // osum
        out[24576 + 2 * i]     = lx;   out[24576 + 2 * i + 1] = ly;   // left
        out[32768 + 2 * i]     = rx;   out[32768 + 2 * i + 1] = ry;   // right
    }
}

// ---------------- K2: collision solve, single block, shared positions ------
__global__ void __launch_bounds__(1024) k_collide(float* __restrict__ out) {
    __shared__ float2 sp[NPART];
    int t = threadIdx.x;
#pragma unroll
    for (int k = 0; k < 4; k++) sp[t + 1024 * k] = g_p0[t + 1024 * k];
    int cnts[4];
#pragma unroll
    for (int k = 0; k < 4; k++) cnts[k] = g_ncnt[t + 1024 * k];
    __syncthreads();

    const float C2  = (float)(6.3e-6 * 6.3e-6);   // (2*RC)^2
    const float TRC = 6.615e-6f;                  // 2.1*RC

    for (int it = 0; it < 30; it++) {
        bool any = false;
        float2 npv[4];
#pragma unroll
        for (int k = 0; k < 4; k++) {
            int i = t + 1024 * k;
            float2 p = sp[i];
            float mx = 0.f, my = 0.f;
            int c = cnts[k];
            for (int q = 0; q < c; q++) {
                int j = g_nb[i * MAXNB + q];
                float2 pj = sp[j];
                float dx = pj.x - p.x;
                float dy = pj.y - p.y;
                float d2 = dx * dx + dy * dy;
                if (d2 <= C2) {
                    float dd = sqrtf(d2);
                    float s = (TRC - dd) * 0.5f / dd;
                    mx += dx * s; my += dy * s;
                    any = true;
                }
            }
            npv[k] = make_float2(p.x - mx, p.y - my);
        }
        int tot = __syncthreads_count(any ? 1 : 0);  // barrier: all reads done
#pragma unroll
        for (int k = 0; k < 4; k++) sp[t + 1024 * k] = npv[k];
        __syncthreads();                              // writes visible
        if (tot == 0) break;   // moves were zero -> fixed point (== ref cont flag)
    }

#pragma unroll
    for (int k = 0; k < 4; k++) {
        int i = t + 1024 * k;
        out[2 * i]     = sp[i].x;
        out[2 * i + 1] = sp[i].y;
    }
}

// ---------------- launch ----------------------------------------------------
extern "C" void kernel_launch(void* const* d_in, const int* in_sizes, int n_in,
                              void* d_out, int out_size) {
    const float* pre = (const float*)d_in[0];
    const float* pim = (const float*)d_in[1];
    const float* ore = (const float*)d_in[2];
    const float* oim = (const float*)d_in[3];
    const float* del = (const float*)d_in[4];
    const float* rn  = (const float*)d_in[5];
    const float* tnr = (const float*)d_in[6];
    const float* tni = (const float*)d_in[7];
    float* out = (float*)d_out;

    k_prep<<<16, 256>>>(pre, pim, ore, oim);
    k_mean<<<1, 1024>>>(pre, pim);
    k_main<<<512, 256>>>(ore, oim, del, rn, tnr, tni, out);
    k_collide<<<1, 1024>>>(out);
}

// round 4
// speedup vs baseline: 1.8263x; 1.8263x over previous
#include <cuda_runtime.h>
#include <math.h>

#define NPART 4096
#define MAXNB 48

// ---------------- device scratch (no allocations allowed) ----------------
__device__ float2 g_pos[NPART];          // packed original positions
__device__ float  g_ang[NPART];          // atan2(ori_im, ori_re)
__device__ float2 g_p0[NPART];           // pos + trans (collision input)
__device__ float2 g_mean;                // global position mean (cms)
__device__ int    g_nb[NPART * MAXNB];   // collision candidate lists
__device__ int    g_ncnt[NPART];

// ---------------- constants (match reference float32 semantics) ----------
#define PI_F      3.1415927410125732f
#define TWO_PI_F  6.2831854820251465f
#define HALF_PI_F 1.5707963705062866f

__device__ __forceinline__ float wrapf(float diff) {
    // matches: where(diff <= -pi, mod(diff, pi), diff); then -2pi if >= pi
    if (diff <= -PI_F) {
        float m = fmodf(diff, PI_F);       // C fmod: sign of dividend
        if (m < 0.0f) m += PI_F;           // -> pythonic mod in [0, pi)
        diff = m;
    }
    if (diff >= PI_F) diff -= TWO_PI_F;
    return diff;
}

// ---------------- K0: pack positions, angles, global mean ------------------
__global__ void __launch_bounds__(1024) k_prep(
    const float* __restrict__ pre, const float* __restrict__ pim,
    const float* __restrict__ ore, const float* __restrict__ oim) {
    __shared__ float sx[1024], sy[1024];
    int t = threadIdx.x;
    float ax = 0.f, ay = 0.f;
#pragma unroll
    for (int k = 0; k < 4; k++) {
        int i = t + 1024 * k;
        float x = pre[i], y = pim[i];
        g_pos[i] = make_float2(x, y);
        g_ang[i] = atan2f(oim[i], ore[i]);
        ax += x; ay += y;
    }
    sx[t] = ax; sy[t] = ay;
    __syncthreads();
    for (int s = 512; s > 0; s >>= 1) {
        if (t < s) { sx[t] += sx[t + s]; sy[t] += sy[t + s]; }
        __syncthreads();
    }
    if (t == 0) g_mean = make_float2(sx[0] * (1.0f / 4096.0f), sy[0] * (1.0f / 4096.0f));
}

// ---------------- K1: N^2 pair pass + per-particle epilogue ----------------
__global__ void __launch_bounds__(256) k_main(
    const float* __restrict__ ore, const float* __restrict__ oim,
    const float* __restrict__ deltas, const float* __restrict__ rotn,
    const float* __restrict__ tnr, const float* __restrict__ tni,
    float* __restrict__ out)
{
    const float RO_RC2 = (float)(2.815e-5 * 2.815e-5);   // (RO+RC)^2
    const float RR2    = (float)(8.0e-6 * 8.0e-6);       // RR^2
    const float NB2    = (float)(2.52e-5 * 2.52e-5);     // (8*RC)^2 candidate radius

    __shared__ float2 spos[NPART];                        // 32 KB tile: whole system
    for (int k = threadIdx.x; k < NPART; k += 256) spos[k] = g_pos[k];
    __syncthreads();

    int warp = threadIdx.x >> 5;
    int lane = threadIdx.x & 31;
    int i = blockIdx.x * 8 + warp;

    float2 pi_ = spos[i];
    float  angi = g_ang[i];

    float osr = 0.f, osi = 0.f, sx = 0.f, sy = 0.f;
    int nr = 0, cnt = 0;
    unsigned lmask = (1u << lane) - 1u;
    const float4* sp4 = reinterpret_cast<const float4*>(spos);

#pragma unroll 4
    for (int jj = lane; jj < NPART / 2; jj += 32) {
        float4 v = sp4[jj];                    // particles 2jj, 2jj+1
        int jA = 2 * jj, jB = 2 * jj + 1;
        float dxA = v.x - pi_.x, dyA = v.y - pi_.y;
        float dxB = v.z - pi_.x, dyB = v.w - pi_.y;
        float d2A = fmaf(dxA, dxA, dyA * dyA);
        float d2B = fmaf(dxB, dxB, dyB * dyB);
        bool roA = (d2A <= RO_RC2), roB = (d2B <= RO_RC2);
        unsigned mro = __ballot_sync(0xffffffffu, roA || roB);
        if (mro) {   // rare branch (~5% of iterations), warp-uniform
            bool nbA = roA && (d2A <= NB2) && (jA != i);
            bool nbB = roB && (d2B <= NB2) && (jB != i);
            unsigned mA = __ballot_sync(0xffffffffu, nbA);
            unsigned mB = __ballot_sync(0xffffffffu, nbB);
            if (nbA) {
                int idx = cnt + __popc(mA & lmask);
                if (idx < MAXNB) g_nb[i * MAXNB + idx] = jA;
            }
            cnt += __popc(mA);
            if (nbB) {
                int idx = cnt + __popc(mB & lmask);
                if (idx < MAXNB) g_nb[i * MAXNB + idx] = jB;
            }
            cnt += __popc(mB);
            if (roA) {
                osr += __ldg(&ore[jA]); osi += __ldg(&oim[jA]);
                if (d2A <= RR2 && jA != i) {
                    float ad = wrapf(angi - __ldg(&g_ang[jA]));
                    if (fabsf(ad) < HALF_PI_F) { nr += 1; sx += v.x; sy += v.y; }
                }
            }
            if (roB) {
                osr += __ldg(&ore[jB]); osi += __ldg(&oim[jB]);
                if (d2B <= RR2 && jB != i) {
                    float ad = wrapf(angi - __ldg(&g_ang[jB]));
                    if (fabsf(ad) < HALF_PI_F) { nr += 1; sx += v.z; sy += v.w; }
                }
            }
        }
    }

    // warp reduction
#pragma unroll
    for (int o = 16; o > 0; o >>= 1) {
        osr += __shfl_down_sync(0xffffffffu, osr, o);
        osi += __shfl_down_sync(0xffffffffu, osi, o);
        sx  += __shfl_down_sync(0xffffffffu, sx,  o);
        sy  += __shfl_down_sync(0xffffffffu, sy,  o);
        nr  += __shfl_down_sync(0xffffffffu, nr,  o);
    }

    if (lane == 0) {
        g_ncnt[i] = (cnt < MAXNB) ? cnt : MAXNB;

        float2 mean = g_mean;
        float invn = 1.0f / fmaxf((float)nr, 1.0f);
        float sgn  = (nr > 0) ? 1.0f : 0.0f;
        float Sx = sx * invn - pi_.x * sgn;
        float Sy = sy * invn - pi_.y * sgn;
        float dxr = -Sx, dyr = -Sy;

        float Psx = mean.x - pi_.x;
        float Psy = mean.y - pi_.y;

        float del = deltas[i];
        float cd, sd; sincosf(del, &sd, &cd);
        float lx = Psx * cd - Psy * sd;            // Ps * exp(+i delta)
        float ly = Psx * sd + Psy * cd;
        float rx = Psx * cd + Psy * sd;            // Ps * exp(-i delta)
        float ry = Psy * cd - Psx * sd;

        float no  = fmaxf(sqrtf(osr * osr + osi * osi), 1e-14f);
        float nl  = fmaxf(sqrtf(lx * lx + ly * ly), 1e-14f);
        float nrt = fmaxf(sqrtf(rx * rx + ry * ry), 1e-14f);
        float csl = (lx * osr + ly * osi) / (nl * no);
        float csr = (rx * osr + ry * osi) / (nrt * no);
        float bx = (csl >= csr) ? lx : rx;
        float by = (csl >= csr) ? ly : ry;

        bool hasrep = (dxr * dxr + dyr * dyr) > 0.0f;
        float aa  = hasrep ? atan2f(dyr, dxr) : atan2f(by, bx);
        float att = wrapf(aa - angi);

        float theta = 0.014f * sinf(att)
                    + (rotn[i] * 0.074833147735478508f) * 0.44721359549995793f;
        float cr, sr; sincosf(theta, &sr, &cr);
        float oxi = ore[i], oyi = oim[i];
        float nor = oxi * cr - oyi * sr;           // new_ori = ori * rot
        float noi = oxi * sr + oyi * cr;

        float tnx = ((tnr[i] * 0.70710678118654752f) * 1.6733200530681511e-7f)
                    * 0.44721359549995793f;
        float tny = ((tni[i] * 0.70710678118654752f) * 1.6733200530681511e-7f)
                    * 0.44721359549995793f;
        float trx = 1e-7f * oxi + tnx;             // DT*VEL*ori + tnoise*sqrt(DT)
        float try_ = 1e-7f * oyi + tny;

        g_p0[i] = make_float2(pi_.x + trx, pi_.y + try_);

        out[ 8192 + 2 * i]     = nor;  out[ 8192 + 2 * i + 1] = noi;  // new_ori
        out[16384 + 2 * i]     = osr;  out[16384 + 2 * i + 1] = osi;  // osum
        out[24576 + 2 * i]     = lx;   out[24576 + 2 * i + 1] = ly;   // left
        out[32768 + 2 * i]     = rx;   out[32768 + 2 * i + 1] = ry;   // right
    }
}

// ---------------- K2: collision solve, single block, activity-masked -------
__global__ void __launch_bounds__(1024) k_collide(float* __restrict__ out) {
    __shared__ float2 sp[NPART];                 // 32 KB positions
    __shared__ unsigned char needA[NPART];       // 4 KB  activity flags (double buffer)
    __shared__ unsigned char needB[NPART];       // 4 KB

    int t = threadIdx.x;
    int cnts[4];
#pragma unroll
    for (int k = 0; k < 4; k++) {
        int i = t + 1024 * k;
        sp[i] = g_p0[i];
        needA[i] = 1;      // everyone active at iteration 0
        needB[i] = 0;
        cnts[k] = g_ncnt[i];
    }
    __syncthreads();

    unsigned char* cur = needA;
    unsigned char* nxt = needB;

    const float C2  = (float)(6.3e-6 * 6.3e-6);   // (2*RC)^2
    const float TRC = 6.615e-6f;                  // 2.1*RC

    for (int it = 0; it < 30; it++) {
        bool moved_any = false;
        float2 npv[4];
        bool   mv[4];
#pragma unroll
        for (int k = 0; k < 4; k++) {
            int i = t + 1024 * k;
            float2 p = sp[i];
            npv[k] = p;
            mv[k] = false;
            if (cur[i]) {
                int c = cnts[k];
                if (c > 0) {
                    const int base = i * MAXNB;
                    float mx = 0.f, my = 0.f;
                    int j = g_nb[base];                       // prefetch head
                    for (int q = 0; q < c; q++) {
                        int jn = (q + 1 < c) ? g_nb[base + q + 1] : 0;  // overlap LDG
                        float2 pj = sp[j];
                        float dx = pj.x - p.x;
                        float dy = pj.y - p.y;
                        float d2 = dx * dx + dy * dy;
                        if (d2 <= C2) {
                            float dd = sqrtf(d2);
                            float s = (TRC - dd) * 0.5f / dd;
                            mx += dx * s; my += dy * s;
                            mv[k] = true;
                        }
                        j = jn;
                    }
                    if (mv[k]) {
                        npv[k] = make_float2(p.x - mx, p.y - my);
                        moved_any = true;
                    }
                }
            }
        }
        int tot = __syncthreads_count(moved_any ? 1 : 0);   // all reads done
        // apply moves, scatter next-iteration activity, clear old flags
#pragma unroll
        for (int k = 0; k < 4; k++) {
            int i = t + 1024 * k;
            sp[i] = npv[k];
            cur[i] = 0;                   // cur becomes nxt after swap; safe: compute phase over
            if (mv[k]) {
                nxt[i] = 1;
                int c = cnts[k];
                const int base = i * MAXNB;
                for (int q = 0; q < c; q++) nxt[g_nb[base + q]] = 1;  // benign races (all write 1)
            }
        }
        __syncthreads();
        if (tot == 0) break;              // no collisions anywhere -> fixed point (== ref)
        unsigned char* tmp = cur; cur = nxt; nxt = tmp;
    }

#pragma unroll
    for (int k = 0; k < 4; k++) {
        int i = t + 1024 * k;
        out[2 * i]     = sp[i].x;
        out[2 * i + 1] = sp[i].y;
    }
}

// ---------------- launch ----------------------------------------------------
extern "C" void kernel_launch(void* const* d_in, const int* in_sizes, int n_in,
                              void* d_out, int out_size) {
    const float* pre = (const float*)d_in[0];
    const float* pim = (const float*)d_in[1];
    const float* ore = (const float*)d_in[2];
    const float* oim = (const float*)d_in[3];
    const float* del = (const float*)d_in[4];
    const float* rn  = (const float*)d_in[5];
    const float* tnr = (const float*)d_in[6];
    const float* tni = (const float*)d_in[7];
    float* out = (float*)d_out;

    k_prep<<<1, 1024>>>(pre, pim, ore, oim);
    k_main<<<512, 256>>>(ore, oim, del, rn, tnr, tni, out);
    k_collide<<<1, 1024>>>(out);
}

// round 6
// speedup vs baseline: 2.0461x; 1.1203x over previous
#include <cuda_runtime.h>
#include <math.h>

#define NPART 4096
#define MAXNB 48

// ---------------- device scratch (no allocations allowed) ----------------
__device__ float2 g_p0[NPART];           // pos + trans (collision input)
__device__ int    g_nb[NPART * MAXNB];   // collision candidate lists (192B rows, int4-aligned)
__device__ int    g_ncnt[NPART];

// ---------------- constants (match reference float32 semantics) ----------
#define PI_F      3.1415927410125732f
#define TWO_PI_F  6.2831854820251465f

__device__ __forceinline__ float wrapf(float diff) {
    // matches: where(diff <= -pi, mod(diff, pi), diff); then -2pi if >= pi
    if (diff <= -PI_F) {
        float m = fmodf(diff, PI_F);       // C fmod: sign of dividend
        if (m < 0.0f) m += PI_F;           // -> pythonic mod in [0, pi)
        diff = m;
    }
    if (diff >= PI_F) diff -= TWO_PI_F;
    return diff;
}

// ---------------- K1: N^2 pair pass + per-particle epilogue ----------------
// One warp per particle. 128 blocks x 32 warps = 4096 particles.
// Each block stages all positions in smem and redundantly computes the global
// mean (cheaper than a separate grid=1 prep kernel + launch gap).
__global__ void __launch_bounds__(1024) k_main(
    const float* __restrict__ pre, const float* __restrict__ pim,
    const float* __restrict__ ore, const float* __restrict__ oim,
    const float* __restrict__ deltas, const float* __restrict__ rotn,
    const float* __restrict__ tnr, const float* __restrict__ tni,
    float* __restrict__ out)
{
    const float RO_RC2 = (float)(2.815e-5 * 2.815e-5);   // (RO+RC)^2
    const float RR2    = (float)(8.0e-6 * 8.0e-6);       // RR^2
    const float NB2    = (float)(2.52e-5 * 2.52e-5);     // (8*RC)^2 candidate radius

    __shared__ float2 spos[NPART];   // 32 KB: whole system
    __shared__ float  swx[32], swy[32];
    __shared__ float2 smean;

    int t    = threadIdx.x;
    int warp = t >> 5;
    int lane = t & 31;

    // stage positions + partial mean sums
    float ax = 0.f, ay = 0.f;
#pragma unroll
    for (int k = 0; k < 4; k++) {
        int idx = t + 1024 * k;
        float x = pre[idx], y = pim[idx];
        spos[idx] = make_float2(x, y);
        ax += x; ay += y;
    }
#pragma unroll
    for (int o = 16; o > 0; o >>= 1) {
        ax += __shfl_down_sync(0xffffffffu, ax, o);
        ay += __shfl_down_sync(0xffffffffu, ay, o);
    }
    if (lane == 0) { swx[warp] = ax; swy[warp] = ay; }
    __syncthreads();                       // spos + swx visible
    if (warp == 0) {
        float bx = swx[lane], by = swy[lane];
#pragma unroll
        for (int o = 16; o > 0; o >>= 1) {
            bx += __shfl_down_sync(0xffffffffu, bx, o);
            by += __shfl_down_sync(0xffffffffu, by, o);
        }
        if (lane == 0) smean = make_float2(bx * (1.0f / 4096.0f), by * (1.0f / 4096.0f));
    }
    __syncthreads();                       // smean visible

    int i = blockIdx.x * 32 + warp;
    float2 pi_ = spos[i];
    float  orx = __ldg(&ore[i]), ory = __ldg(&oim[i]);   // own orientation

    float osr = 0.f, osi = 0.f, sx = 0.f, sy = 0.f;
    int nr = 0, cnt = 0;
    unsigned lmask = (1u << lane) - 1u;
    const float4* sp4 = reinterpret_cast<const float4*>(spos);

#pragma unroll 4
    for (int jj = lane; jj < NPART / 2; jj += 32) {
        float4 v = sp4[jj];                    // particles 2jj, 2jj+1
        int jA = 2 * jj, jB = 2 * jj + 1;
        float dxA = v.x - pi_.x, dyA = v.y - pi_.y;
        float dxB = v.z - pi_.x, dyB = v.w - pi_.y;
        float d2A = fmaf(dxA, dxA, dyA * dyA);
        float d2B = fmaf(dxB, dxB, dyB * dyB);
        bool roA = (d2A <= RO_RC2), roB = (d2B <= RO_RC2);
        unsigned mro = __ballot_sync(0xffffffffu, roA || roB);
        if (mro) {   // rare branch (~9% of iterations), warp-uniform
            bool nbA = roA && (d2A <= NB2) && (jA != i);
            bool nbB = roB && (d2B <= NB2) && (jB != i);
            unsigned mA = __ballot_sync(0xffffffffu, nbA);
            unsigned mB = __ballot_sync(0xffffffffu, nbB);
            if (nbA) {
                int idx = cnt + __popc(mA & lmask);
                if (idx < MAXNB) g_nb[i * MAXNB + idx] = jA;
            }
            cnt += __popc(mA);
            if (nbB) {
                int idx = cnt + __popc(mB & lmask);
                if (idx < MAXNB) g_nb[i * MAXNB + idx] = jB;
            }
            cnt += __popc(mB);
            if (roA) {
                float ojx = __ldg(&ore[jA]), ojy = __ldg(&oim[jA]);
                osr += ojx; osi += ojy;
                if (d2A <= RR2 && jA != i) {
                    // |wrap(ang_i-ang_j)| < pi/2  <=>  dot(ori_i, ori_j) > 0
                    if (orx * ojx + ory * ojy > 0.0f) { nr += 1; sx += v.x; sy += v.y; }
                }
            }
            if (roB) {
                float ojx = __ldg(&ore[jB]), ojy = __ldg(&oim[jB]);
                osr += ojx; osi += ojy;
                if (d2B <= RR2 && jB != i) {
                    if (orx * ojx + ory * ojy > 0.0f) { nr += 1; sx += v.z; sy += v.w; }
                }
            }
        }
    }

    // warp reduction
#pragma unroll
    for (int o = 16; o > 0; o >>= 1) {
        osr += __shfl_down_sync(0xffffffffu, osr, o);
        osi += __shfl_down_sync(0xffffffffu, osi, o);
        sx  += __shfl_down_sync(0xffffffffu, sx,  o);
        sy  += __shfl_down_sync(0xffffffffu, sy,  o);
        nr  += __shfl_down_sync(0xffffffffu, nr,  o);
    }

    if (lane == 0) {
        g_ncnt[i] = (cnt < MAXNB) ? cnt : MAXNB;

        float angi = atan2f(ory, orx);
        float2 mean = smean;
        float invn = 1.0f / fmaxf((float)nr, 1.0f);
        float sgn  = (nr > 0) ? 1.0f : 0.0f;
        float Sx = sx * invn - pi_.x * sgn;
        float Sy = sy * invn - pi_.y * sgn;
        float dxr = -Sx, dyr = -Sy;

        float Psx = mean.x - pi_.x;
        float Psy = mean.y - pi_.y;

        float del = deltas[i];
        float cd, sd; sincosf(del, &sd, &cd);
        float lx = Psx * cd - Psy * sd;            // Ps * exp(+i delta)
        float ly = Psx * sd + Psy * cd;
        float rx = Psx * cd + Psy * sd;            // Ps * exp(-i delta)
        float ry = Psy * cd - Psx * sd;

        float no  = fmaxf(sqrtf(osr * osr + osi * osi), 1e-14f);
        float nl  = fmaxf(sqrtf(lx * lx + ly * ly), 1e-14f);
        float nrt = fmaxf(sqrtf(rx * rx + ry * ry), 1e-14f);
        float csl = (lx * osr + ly * osi) / (nl * no);
        float csr = (rx * osr + ry * osi) / (nrt * no);
        float bx = (csl >= csr) ? lx : rx;
        float by = (csl >= csr) ? ly : ry;

        bool hasrep = (dxr * dxr + dyr * dyr) > 0.0f;
        float aa  = hasrep ? atan2f(dyr, dxr) : atan2f(by, bx);
        float att = wrapf(aa - angi);

        float theta = 0.014f * sinf(att)
                    + (rotn[i] * 0.074833147735478508f) * 0.44721359549995793f;
        float cr, sr; sincosf(theta, &sr, &cr);
        float nor = orx * cr - ory * sr;           // new_ori = ori * rot
        float noi = orx * sr + ory * cr;

        float tnx = ((tnr[i] * 0.70710678118654752f) * 1.6733200530681511e-7f)
                    * 0.44721359549995793f;
        float tny = ((tni[i] * 0.70710678118654752f) * 1.6733200530681511e-7f)
                    * 0.44721359549995793f;
        float trx = 1e-7f * orx + tnx;             // DT*VEL*ori + tnoise*sqrt(DT)
        float try_ = 1e-7f * ory + tny;

        g_p0[i] = make_float2(pi_.x + trx, pi_.y + try_);

        out[ 8192 + 2 * i]     = nor;  out[ 8192 + 2 * i + 1] = noi;  // new_ori
        out[16384 + 2 * i]     = osr;  out[16384 + 2 * i + 1] = osi;  // osum
        out[24576 + 2 * i]     = lx;   out[24576 + 2 * i + 1] = ly;   // left
        out[32768 + 2 * i]     = rx;   out[32768 + 2 * i + 1] = ry;   // right
    }
}

// ---------------- K2: collision solve, single block, epoch-masked ----------
__global__ void __launch_bounds__(1024) k_collide(float* __restrict__ out) {
    __shared__ float2 sp[NPART];                 // 32 KB positions
    __shared__ unsigned char mark[NPART];        // 4 KB epoch flags (no per-iter clearing)

    int t = threadIdx.x;
    int cnts[4];
#pragma unroll
    for (int k = 0; k < 4; k++) {
        int i = t + 1024 * k;
        sp[i] = g_p0[i];
        mark[i] = 0;                              // active at iteration 0
        cnts[k] = g_ncnt[i];
    }
    __syncthreads();

    const float C2  = (float)(6.3e-6 * 6.3e-6);   // (2*RC)^2
    const float TRC = 6.615e-6f;                  // 2.1*RC

    for (int it = 0; it < 30; it++) {
        bool moved_any = false;
        float2 npv[4];
        bool   mv[4];
        unsigned char ep = (unsigned char)it;
#pragma unroll
        for (int k = 0; k < 4; k++) {
            int i = t + 1024 * k;
            mv[k] = false;
            if (mark[i] == ep) {
                int c = cnts[k];
                if (c > 0) {
                    float2 p = sp[i];
                    float mx = 0.f, my = 0.f;
                    const int4* nb4 = reinterpret_cast<const int4*>(&g_nb[i * MAXNB]);
                    for (int q = 0; q < c; q += 4) {
                        int4 j4 = nb4[q >> 2];    // MLP-4 index fetch
                        int js[4] = { j4.x, j4.y, j4.z, j4.w };
#pragma unroll
                        for (int r = 0; r < 4; r++) {
                            if (q + r < c) {
                                float2 pj = sp[js[r]];
                                float dx = pj.x - p.x;
                                float dy = pj.y - p.y;
                                float d2 = dx * dx + dy * dy;
                                if (d2 <= C2) {
                                    float dd = sqrtf(d2);
                                    float s = (TRC - dd) * 0.5f / dd;
                                    mx += dx * s; my += dy * s;
                                    mv[k] = true;
                                }
                            }
                        }
                    }
                    if (mv[k]) {
                        npv[k] = make_float2(p.x - mx, p.y - my);
                        moved_any = true;
                    }
                }
            }
        }
        int tot = __syncthreads_count(moved_any ? 1 : 0);   // all reads of sp/mark done
        if (tot == 0) break;          // no collisions anywhere -> fixed point (== ref cont)
        unsigned char epn = (unsigned char)(it + 1);
#pragma unroll
        for (int k = 0; k < 4; k++) {
            if (mv[k]) {
                int i = t + 1024 * k;
                sp[i] = npv[k];
                mark[i] = epn;
                int c = cnts[k];
                const int base = i * MAXNB;
                for (int q = 0; q < c; q++) mark[g_nb[base + q]] = epn;  // benign same-value races
            }
        }
        __syncthreads();              // writes visible before next compute phase
    }

#pragma unroll
    for (int k = 0; k < 4; k++) {
        int i = t + 1024 * k;
        out[2 * i]     = sp[i].x;
        out[2 * i + 1] = sp[i].y;
    }
}

// ---------------- launch ----------------------------------------------------
extern "C" void kernel_launch(void* const* d_in, const int* in_sizes, int n_in,
                              void* d_out, int out_size) {
    const float* pre = (const float*)d_in[0];
    const float* pim = (const float*)d_in[1];
    const float* ore = (const float*)d_in[2];
    const float* oim = (const float*)d_in[3];
    const float* del = (const float*)d_in[4];
    const float* rn  = (const float*)d_in[5];
    const float* tnr = (const float*)d_in[6];
    const float* tni = (const float*)d_in[7];
    float* out = (float*)d_out;

    k_main<<<128, 1024>>>(pre, pim, ore, oim, del, rn, tnr, tni, out);
    k_collide<<<1, 1024>>>(out);
}